// round 14
// baseline (speedup 1.0000x reference)
#include <cuda_runtime.h>
#include <cuda_bf16.h>
#include <cstdint>

#define Bsz   4
#define Cc    256
#define CE    64
#define Tt    16
#define Hh    56
#define Ww    56
#define HW    3136
#define THW   50176
#define Gg    4
#define K2G   196
#define KPAD  224            // 28 islands of 8 (g*56 + ky*8 + kx, kx<7 valid)
#define EPSI  1e-5f

// Scratch (device globals: allocation-free rule)
__device__ uint16_t g_xencb[(size_t)Bsz * CE * THW];      // x_enc bf16
__device__ uint16_t g_xcorrb[(size_t)Bsz * THW * KPAD];   // [pixel][k''] bf16
__device__ uint16_t g_dwb[Cc * KPAD];                     // dec_w permuted bf16
__device__ uint32_t g_wt[CE * Cc];                        // enc_w tf32 bits

__device__ __forceinline__ void cp_async16(uint32_t smem_addr, const void* gptr, int src_bytes) {
    asm volatile("cp.async.cg.shared.global [%0], [%1], 16, %2;"
                 :: "r"(smem_addr), "l"(gptr), "r"(src_bytes));
}
__device__ __forceinline__ void cp_commit() { asm volatile("cp.async.commit_group;"); }
__device__ __forceinline__ void cp_wait0()  { asm volatile("cp.async.wait_group 0;"); }
__device__ __forceinline__ void cp_wait1()  { asm volatile("cp.async.wait_group 1;"); }
__device__ __forceinline__ void cp_wait2()  { asm volatile("cp.async.wait_group 2;"); }

__device__ __forceinline__ uint32_t tf32rna(float f) {
    uint32_t r; asm("cvt.rna.tf32.f32 %0, %1;" : "=r"(r) : "f"(f)); return r;
}
__device__ __forceinline__ uint32_t bf2(float lo, float hi) {
    uint32_t r; asm("cvt.rn.bf16x2.f32 %0, %1, %2;" : "=r"(r) : "f"(hi), "f"(lo));
    return r;
}
__device__ __forceinline__ float bflo(uint32_t w) { return __uint_as_float(w << 16); }
__device__ __forceinline__ float bfhi(uint32_t w) { return __uint_as_float(w & 0xFFFF0000u); }
__device__ __forceinline__ uint32_t smem_u32(const void* p) {
    return (uint32_t)__cvta_generic_to_shared(p);
}
__device__ __forceinline__ void mma_tf32(float* c, const uint32_t* a, const uint32_t* b) {
    asm volatile(
        "mma.sync.aligned.m16n8k8.row.col.f32.tf32.tf32.f32 "
        "{%0,%1,%2,%3}, {%4,%5,%6,%7}, {%8,%9}, {%0,%1,%2,%3};"
        : "+f"(c[0]), "+f"(c[1]), "+f"(c[2]), "+f"(c[3])
        : "r"(a[0]), "r"(a[1]), "r"(a[2]), "r"(a[3]), "r"(b[0]), "r"(b[1]));
}
__device__ __forceinline__ void mma_bf16(float* c, const uint32_t* a, const uint32_t* b) {
    asm volatile(
        "mma.sync.aligned.m16n8k16.row.col.f32.bf16.bf16.f32 "
        "{%0,%1,%2,%3}, {%4,%5,%6,%7}, {%8,%9}, {%0,%1,%2,%3};"
        : "+f"(c[0]), "+f"(c[1]), "+f"(c[2]), "+f"(c[3])
        : "r"(a[0]), "r"(a[1]), "r"(a[2]), "r"(a[3]), "r"(b[0]), "r"(b[1]));
}
__device__ __forceinline__ void ldsm_x4(uint32_t* r, uint32_t addr) {
    asm volatile("ldmatrix.sync.aligned.m8n8.x4.shared.b16 {%0,%1,%2,%3}, [%4];"
                 : "=r"(r[0]), "=r"(r[1]), "=r"(r[2]), "=r"(r[3]) : "r"(addr));
}
// tf32 f32-tile swizzle (enc A)
__device__ __forceinline__ int swoff(int r, int k) {
    return r * 32 + ((((k >> 2) ^ r) & 7) << 2) + (k & 3);
}

// ---------------------------------------------------------------------------
// Kernel 0: prep — dec_w -> bf16 islands; enc_w -> tf32 bits
// ---------------------------------------------------------------------------
__global__ void prep_kernel(const float* __restrict__ dw, const float* __restrict__ ew)
{
    int idx = blockIdx.x * 256 + threadIdx.x;
    if (idx < Cc * KPAD) {
        int m = idx / KPAD, kp = idx % KPAD;
        int g = kp / 56, rem = kp % 56;
        int ky = rem / 8, kx = rem % 8;
        float v = 0.f;
        if (kx < 7) v = dw[m * K2G + (ky * 7 + kx) * 4 + g];
        g_dwb[idx] = (uint16_t)(bf2(v, 0.f) & 0xFFFF);
    } else if (idx < Cc * KPAD + CE * Cc) {
        int j = idx - Cc * KPAD;
        g_wt[j] = tf32rna(ew[j]);
    }
}

// ---------------------------------------------------------------------------
// Kernel 1: enc 1x1 conv on mma.sync tf32, BN=128 (3 CTAs/SM).
// BM=64(CE), BN=128, 256 thr = 8 warps (warp tile 64m x 16n).
// smem/stage: A 8KB (f32 swizzled) + B 16KB (32k x 128n f32); 2 stages.
// ---------------------------------------------------------------------------
#define E_SMEM (2 * (8192 + 16384))     // 49152
#define E_AST(s) ((s) * 8192)
#define E_BST(s) (16384 + (s) * 16384)

__global__ void __launch_bounds__(256, 3) enc_kernel(
    const float* __restrict__ x,
    const float* __restrict__ eg, const float* __restrict__ eb,
    const float* __restrict__ em, const float* __restrict__ ev)
{
    extern __shared__ char esm[];
    const int t = threadIdx.x;
    const int wid = t >> 5, lane = t & 31;
    const int warpN = wid;                 // 16 n each
    const int n0 = blockIdx.x * 128;
    const int b  = blockIdx.y;

    const float* xb = x + (size_t)b * Cc * THW;

    float cacc[4][2][4];
    #pragma unroll
    for (int i = 0; i < 4; i++)
        #pragma unroll
        for (int j = 0; j < 2; j++)
            #pragma unroll
            for (int r = 0; r < 4; r++) cacc[i][j][r] = 0.f;

    int bpos[2];
    #pragma unroll
    for (int nt = 0; nt < 2; nt++) {
        int n = warpN * 16 + nt * 8 + (lane >> 2);
        bpos[nt] = (((n >> 2) ^ (2 * (lane & 3))) << 2) + (n & 3);
    }

    auto load_chunk = [&](int kc, int s) {
        // A: 64 rows x 8 16B-chunks = 512, 2/thread
        #pragma unroll
        for (int i = 0; i < 2; i++) {
            int e = t + 256 * i;
            int r = e >> 3, c = e & 7;
            cp_async16(smem_u32(esm + E_AST(s) + r * 128 + (((c ^ r) & 7) << 4)),
                       g_wt + r * Cc + kc * 32 + c * 4, 16);
        }
        // B: 32 k-rows x 32 16B-chunks = 1024, 4/thread
        #pragma unroll
        for (int i = 0; i < 4; i++) {
            int e = t + 256 * i;
            int k = e >> 5, j = e & 31;
            uint32_t dst = smem_u32(esm + E_BST(s) + k * 512
                                    + ((j ^ (2 * (k & 3))) << 4));
            cp_async16(dst, xb + (size_t)(kc * 32 + k) * THW + n0 + j * 4, 16);
        }
    };

    load_chunk(0, 0);
    cp_commit();

    for (int c = 0; c < 8; c++) {
        const int s = c & 1;
        if (c > 0) __syncthreads();
        if (c + 1 < 8) { load_chunk(c + 1, s ^ 1); cp_commit(); cp_wait1(); }
        else cp_wait0();
        __syncthreads();

        const uint32_t* Ab = reinterpret_cast<const uint32_t*>(esm + E_AST(s));
        const uint32_t* Bb = reinterpret_cast<const uint32_t*>(esm + E_BST(s));

        #pragma unroll
        for (int ks = 0; ks < 4; ks++) {
            const int kf = ks * 8 + (lane & 3);
            uint32_t bfr[2][2];
            #pragma unroll
            for (int nt = 0; nt < 2; nt++) {
                bfr[nt][0] = tf32rna(__uint_as_float(Bb[kf * 128 + bpos[nt]]));
                bfr[nt][1] = tf32rna(__uint_as_float(Bb[(kf + 4) * 128 + bpos[nt]]));
            }
            #pragma unroll
            for (int mt = 0; mt < 4; mt++) {
                int r = mt * 16 + (lane >> 2);
                uint32_t afr[4];
                afr[0] = Ab[swoff(r,     kf)];
                afr[1] = Ab[swoff(r + 8, kf)];
                afr[2] = Ab[swoff(r,     kf + 4)];
                afr[3] = Ab[swoff(r + 8, kf + 4)];
                #pragma unroll
                for (int nt = 0; nt < 2; nt++)
                    mma_tf32(cacc[mt][nt], afr, bfr[nt]);
            }
        }
    }

    #pragma unroll
    for (int mt = 0; mt < 4; mt++) {
        int ce0 = mt * 16 + (lane >> 2);
        float inv0  = eg[ce0] * rsqrtf(ev[ce0] + EPSI);
        float bias0 = eb[ce0] - em[ce0] * inv0;
        float inv1  = eg[ce0 + 8] * rsqrtf(ev[ce0 + 8] + EPSI);
        float bias1 = eb[ce0 + 8] - em[ce0 + 8] * inv1;
        uint32_t* op0 = reinterpret_cast<uint32_t*>(
            g_xencb + ((size_t)b * CE + ce0)     * THW + n0);
        uint32_t* op1 = reinterpret_cast<uint32_t*>(
            g_xencb + ((size_t)b * CE + ce0 + 8) * THW + n0);
        #pragma unroll
        for (int nt = 0; nt < 2; nt++) {
            int n = warpN * 16 + nt * 8 + (lane & 3) * 2;
            float a0 = fmaxf(cacc[mt][nt][0] * inv0 + bias0, 0.f);
            float a1 = fmaxf(cacc[mt][nt][1] * inv0 + bias0, 0.f);
            float a2 = fmaxf(cacc[mt][nt][2] * inv1 + bias1, 0.f);
            float a3 = fmaxf(cacc[mt][nt][3] * inv1 + bias1, 0.f);
            op0[n >> 1] = bf2(a0, a1);
            op1[n >> 1] = bf2(a2, a3);
        }
    }
}

// ---------------------------------------------------------------------------
// Kernel 2: corr v6 (unchanged from R13)
// ---------------------------------------------------------------------------
#define C_SMEM 54272
#define CX1W(ce, r)    ((ce) * 288 + (r) * 36)
#define CX2W(ce, row)  (4608 + (ce) * 504 + (row) * 36)
#define CWF(ce, ky, k) (12672 + (ce) * 56 + (ky) * 8 + (k))

__global__ void __launch_bounds__(224, 4) corr_kernel(const float* __restrict__ fw)
{
    extern __shared__ float cs[];
    uint32_t* cw = reinterpret_cast<uint32_t*>(cs);
    const int tid = threadIdx.x;
    const int r   = tid & 7;
    const int q   = tid >> 3;
    const int px0 = q * 2;

    const int h0 = blockIdx.x * 8;
    const int tt = blockIdx.y;
    const int b  = blockIdx.z >> 2;
    const int g  = blockIdx.z & 3;
    const int ce0 = g * 16;

    const int t1 = (tt == 0) ? 0 : tt - 1;
    const uint16_t* x1b = g_xencb + (size_t)b * CE * THW + (size_t)t1 * HW;
    const uint16_t* x2b = g_xencb + (size_t)b * CE * THW + (size_t)tt * HW;
    const size_t pixbase = (size_t)b * THW + (size_t)tt * HW + (size_t)h0 * Ww;

    for (int i = tid; i < 16 * 49; i += 224) {
        int ce = i / 49, tap = i % 49;
        cs[CWF(ce, tap / 7, tap % 7)] = fw[((size_t)(ce0 + ce) * Tt + tt) * 49 + tap];
    }
    for (int i = tid; i < 16 * 224; i += 224) {
        int ce = i / 224, rem = i % 224;
        int rr = rem / 28, wi = rem % 28;
        cw[CX1W(ce, rr) + wi] = *reinterpret_cast<const uint32_t*>(
            x1b + (size_t)(ce0 + ce) * THW + (h0 + rr) * Ww + wi * 2);
    }
    for (int i = tid; i < 16 * 448; i += 224) {
        int ce = i / 448, rem = i % 448;
        int row = rem / 32, wi = rem % 32;
        int hy = h0 + row - 3;
        int c0 = wi * 2 - 4;
        uint32_t v = 0;
        if (hy >= 0 && hy < Hh && wi >= 2 && wi <= 29)
            v = *reinterpret_cast<const uint32_t*>(
                x2b + (size_t)(ce0 + ce) * THW + hy * Ww + c0);
        cw[CX2W(ce, row) + wi] = v;
    }
    __syncthreads();

    uint16_t* gb0 = g_xcorrb + (pixbase + r * 56 + px0) * KPAD + (size_t)g * 56;

    #pragma unroll 1
    for (int ky = 0; ky < 7; ky++) {
        float acc[7][2];
        #pragma unroll
        for (int kx = 0; kx < 7; kx++) { acc[kx][0] = 0.f; acc[kx][1] = 0.f; }

        const int zr = r + ky;

        #pragma unroll 4
        for (int ce = 0; ce < 16; ce++) {
            uint32_t yv = cw[CX1W(ce, r) + q];
            float y0 = bflo(yv), y1 = bfhi(yv);
            const uint32_t* zp = &cw[CX2W(ce, zr) + q];
            uint32_t zw0 = zp[0], zw1 = zp[1], zw2 = zp[2], zw3 = zp[3], zw4 = zp[4];
            float z[8];
            z[0] = bfhi(zw0);
            z[1] = bflo(zw1); z[2] = bfhi(zw1);
            z[3] = bflo(zw2); z[4] = bfhi(zw2);
            z[5] = bflo(zw3); z[6] = bfhi(zw3);
            z[7] = bflo(zw4);
            const float* wp = &cs[CWF(ce, ky, 0)];
            float4 w4 = *reinterpret_cast<const float4*>(wp);
            float2 w2 = *reinterpret_cast<const float2*>(wp + 4);
            float  w6 = wp[6];
            float w[7] = {w4.x, w4.y, w4.z, w4.w, w2.x, w2.y, w6};
            #pragma unroll
            for (int kx = 0; kx < 7; kx++) {
                acc[kx][0] += w[kx] * (y0 * z[kx]);
                acc[kx][1] += w[kx] * (y1 * z[kx + 1]);
            }
        }

        const float sc = 1.f / 16.f;
        uint4 v;
        v.x = bf2(acc[0][0] * sc, acc[1][0] * sc);
        v.y = bf2(acc[2][0] * sc, acc[3][0] * sc);
        v.z = bf2(acc[4][0] * sc, acc[5][0] * sc);
        v.w = bf2(acc[6][0] * sc, 0.f);
        *reinterpret_cast<uint4*>(gb0 + ky * 8) = v;
        v.x = bf2(acc[0][1] * sc, acc[1][1] * sc);
        v.y = bf2(acc[2][1] * sc, acc[3][1] * sc);
        v.z = bf2(acc[4][1] * sc, acc[5][1] * sc);
        v.w = bf2(acc[6][1] * sc, 0.f);
        *reinterpret_cast<uint4*>(gb0 + KPAD + ky * 8) = v;
    }
}

// ---------------------------------------------------------------------------
// Kernel 3: dec GEMM bf16 mma + ldmatrix, BN=64, warp tile 32x32 (3 CTAs/SM).
// BM=128, 256 thr = 8 warps (4m x 2n), 3-stage cp.async, m-pair interleave.
// smem/stage: A 8KB + B 4KB = 12KB; 3 stages = 36KB.
// ---------------------------------------------------------------------------
#define D_SMEM (3 * 12288)
#define D_AST(s) ((s) * 12288)
#define D_BST(s) ((s) * 12288 + 8192)

__global__ void __launch_bounds__(256, 3) dec_kernel(
    const float* __restrict__ x,
    const float* __restrict__ dg, const float* __restrict__ db,
    const float* __restrict__ dm, const float* __restrict__ dv,
    float* __restrict__ out)
{
    extern __shared__ char dsm[];
    const int t    = threadIdx.x;
    const int wid  = t >> 5, lane = t & 31;
    const int warpM = wid >> 1;            // 0..3 (32 m each)
    const int warpN = wid & 1;             // 0..1 (32 n each)

    const int nx = blockIdx.x >> 1;        // 784 n-tiles of 64
    const int m0 = (blockIdx.x & 1) * 128;
    const int b  = blockIdx.y;
    const size_t nbase = (size_t)nx * 64;

    const uint16_t* arow = g_dwb + (size_t)m0 * KPAD;
    const uint16_t* brow = g_xcorrb + ((size_t)b * THW + nbase) * KPAD;

    float cacc[2][4][4];
    #pragma unroll
    for (int i = 0; i < 2; i++)
        #pragma unroll
        for (int j = 0; j < 4; j++)
            #pragma unroll
            for (int r = 0; r < 4; r++) cacc[i][j][r] = 0.f;

    const int rowBl = warpN * 32 + lane;   // 0..63
    const int swzB  = ((rowBl >> 1) & 3) << 2;
    const int rAoff = (lane & 7) + ((lane >> 3) & 1) * 8;
    const int khA   = ((lane >> 4) & 1) * 4;

    auto load_chunk = [&](int kc, int s) {
        // A: 128 rows x 4 chunks = 512, 2/thread
        #pragma unroll
        for (int i = 0; i < 2; i++) {
            int e = t + 256 * i;
            int row = e >> 2, c = e & 3;
            uint32_t soff = row * 64 + ((c ^ ((row >> 1) & 3)) << 4);
            cp_async16(smem_u32(dsm + D_AST(s) + soff),
                       arow + (size_t)row * KPAD + kc * 32 + c * 8, 16);
        }
        // B: 64 rows x 4 chunks = 256, 1/thread
        {
            int row = t >> 2, c = t & 3;
            uint32_t soff = row * 64 + ((c ^ ((row >> 1) & 3)) << 4);
            cp_async16(smem_u32(dsm + D_BST(s) + soff),
                       brow + (size_t)row * KPAD + kc * 32 + c * 8, 16);
        }
    };

    load_chunk(0, 0); cp_commit();
    load_chunk(1, 1); cp_commit();

    for (int c = 0; c < 7; c++) {
        const int s = c % 3;
        if (c > 0) __syncthreads();
        if (c + 2 < 7) { load_chunk(c + 2, (c + 2) % 3); cp_commit(); }
        if (c < 5) cp_wait2(); else if (c == 5) cp_wait1(); else cp_wait0();
        __syncthreads();

        const uint32_t* Ab = reinterpret_cast<const uint32_t*>(dsm + D_AST(s));
        const uint32_t* Bb = reinterpret_cast<const uint32_t*>(dsm + D_BST(s));

        #pragma unroll
        for (int ks = 0; ks < 2; ks++) {
            const int kb = ks * 8;
            uint32_t bh0[4], bh1[4];
            ldsm_x4(bh0, smem_u32(Bb + rowBl * 16 + (kb ^ swzB)));
            ldsm_x4(bh1, smem_u32(Bb + rowBl * 16 + ((kb + 4) ^ swzB)));
            #pragma unroll
            for (int mt = 0; mt < 2; mt++) {
                int rowA = warpM * 32 + mt * 16 + rAoff;
                int wA = (kb + khA) ^ (((rowA >> 1) & 3) << 2);
                uint32_t afr[4];
                ldsm_x4(afr, smem_u32(Ab + rowA * 16 + wA));
                #pragma unroll
                for (int nt = 0; nt < 4; nt++) {
                    uint32_t bfr[2] = {bh0[nt], bh1[nt]};
                    mma_bf16(cacc[mt][nt], afr, bfr);
                }
            }
        }
    }

    // Epilogue: BN + residual + ReLU
    #pragma unroll
    for (int mt = 0; mt < 2; mt++) {
        int mrow = m0 + warpM * 32 + mt * 16 + (lane >> 2);
        float inv0  = dg[mrow] * rsqrtf(dv[mrow] + EPSI);
        float bias0 = db[mrow] - dm[mrow] * inv0;
        float inv1  = dg[mrow + 8] * rsqrtf(dv[mrow + 8] + EPSI);
        float bias1 = db[mrow + 8] - dm[mrow + 8] * inv1;
        const float* xr0 = x   + ((size_t)b * Cc + mrow)     * THW + nbase;
        const float* xr1 = x   + ((size_t)b * Cc + mrow + 8) * THW + nbase;
        float*       op0 = out + ((size_t)b * Cc + mrow)     * THW + nbase;
        float*       op1 = out + ((size_t)b * Cc + mrow + 8) * THW + nbase;
        #pragma unroll
        for (int nt = 0; nt < 4; nt++) {
            int n = warpN * 32 + nt * 8 + (lane & 3) * 2;
            float2 r0 = *reinterpret_cast<const float2*>(xr0 + n);
            float2 r1 = *reinterpret_cast<const float2*>(xr1 + n);
            float2 o0, o1;
            o0.x = fmaxf(cacc[mt][nt][0] * inv0 + bias0 + r0.x, 0.f);
            o0.y = fmaxf(cacc[mt][nt][1] * inv0 + bias0 + r0.y, 0.f);
            o1.x = fmaxf(cacc[mt][nt][2] * inv1 + bias1 + r1.x, 0.f);
            o1.y = fmaxf(cacc[mt][nt][3] * inv1 + bias1 + r1.y, 0.f);
            *reinterpret_cast<float2*>(op0 + n) = o0;
            *reinterpret_cast<float2*>(op1 + n) = o1;
        }
    }
}

// ---------------------------------------------------------------------------
extern "C" void kernel_launch(void* const* d_in, const int* in_sizes, int n_in,
                              void* d_out, int out_size)
{
    const float* x     = (const float*)d_in[0];
    const float* enc_w = (const float*)d_in[1];
    const float* eg    = (const float*)d_in[2];
    const float* eb    = (const float*)d_in[3];
    const float* em    = (const float*)d_in[4];
    const float* ev    = (const float*)d_in[5];
    const float* fw    = (const float*)d_in[6];
    const float* dw    = (const float*)d_in[7];
    const float* dg    = (const float*)d_in[8];
    const float* db    = (const float*)d_in[9];
    const float* dm    = (const float*)d_in[10];
    const float* dv    = (const float*)d_in[11];
    float* out = (float*)d_out;

    cudaFuncSetAttribute(enc_kernel,
                         cudaFuncAttributeMaxDynamicSharedMemorySize, E_SMEM);
    cudaFuncSetAttribute(corr_kernel,
                         cudaFuncAttributeMaxDynamicSharedMemorySize, C_SMEM);
    cudaFuncSetAttribute(dec_kernel,
                         cudaFuncAttributeMaxDynamicSharedMemorySize, D_SMEM);

    int prep_n = Cc * KPAD + CE * Cc;
    prep_kernel<<<(prep_n + 255) / 256, 256>>>(dw, enc_w);

    dim3 g1(THW / 128, Bsz);
    enc_kernel<<<g1, 256, E_SMEM>>>(x, eg, eb, em, ev);

    dim3 g2(Hh / 8, Tt, Bsz * Gg);
    corr_kernel<<<g2, 224, C_SMEM>>>(fw);

    dim3 g3(THW / 64 * 2, Bsz);
    dec_kernel<<<g3, 256, D_SMEM>>>(x, dg, db, dm, dv, out);
}

// round 15
// speedup vs baseline: 1.0380x; 1.0380x over previous
#include <cuda_runtime.h>
#include <cuda_bf16.h>
#include <cstdint>

#define Bsz   4
#define Cc    256
#define CE    64
#define Tt    16
#define Hh    56
#define Ww    56
#define HW    3136
#define THW   50176
#define Gg    4
#define K2G   196
#define KPAD  224            // 28 islands of 8 (g*56 + ky*8 + kx, kx<7 valid)
#define EPSI  1e-5f

// Scratch (device globals: allocation-free rule)
__device__ uint16_t g_xencb[(size_t)Bsz * CE * THW];      // x_enc bf16
__device__ uint16_t g_xcorrb[(size_t)Bsz * THW * KPAD];   // [pixel][k''] bf16
__device__ uint16_t g_dwb[Cc * KPAD];                     // dec_w permuted bf16
__device__ uint32_t g_wt[CE * Cc];                        // enc_w tf32 bits

__device__ __forceinline__ void cp_async16(uint32_t smem_addr, const void* gptr, int src_bytes) {
    asm volatile("cp.async.cg.shared.global [%0], [%1], 16, %2;"
                 :: "r"(smem_addr), "l"(gptr), "r"(src_bytes));
}
__device__ __forceinline__ void cp_commit() { asm volatile("cp.async.commit_group;"); }
__device__ __forceinline__ void cp_wait0()  { asm volatile("cp.async.wait_group 0;"); }
__device__ __forceinline__ void cp_wait1()  { asm volatile("cp.async.wait_group 1;"); }

__device__ __forceinline__ uint32_t tf32rna(float f) {
    uint32_t r; asm("cvt.rna.tf32.f32 %0, %1;" : "=r"(r) : "f"(f)); return r;
}
__device__ __forceinline__ uint32_t bf2(float lo, float hi) {
    uint32_t r; asm("cvt.rn.bf16x2.f32 %0, %1, %2;" : "=r"(r) : "f"(hi), "f"(lo));
    return r;
}
__device__ __forceinline__ float bflo(uint32_t w) { return __uint_as_float(w << 16); }
__device__ __forceinline__ float bfhi(uint32_t w) { return __uint_as_float(w & 0xFFFF0000u); }
__device__ __forceinline__ uint32_t smem_u32(const void* p) {
    return (uint32_t)__cvta_generic_to_shared(p);
}
__device__ __forceinline__ void mma_tf32(float* c, const uint32_t* a, const uint32_t* b) {
    asm volatile(
        "mma.sync.aligned.m16n8k8.row.col.f32.tf32.tf32.f32 "
        "{%0,%1,%2,%3}, {%4,%5,%6,%7}, {%8,%9}, {%0,%1,%2,%3};"
        : "+f"(c[0]), "+f"(c[1]), "+f"(c[2]), "+f"(c[3])
        : "r"(a[0]), "r"(a[1]), "r"(a[2]), "r"(a[3]), "r"(b[0]), "r"(b[1]));
}
__device__ __forceinline__ void mma_bf16(float* c, const uint32_t* a, const uint32_t* b) {
    asm volatile(
        "mma.sync.aligned.m16n8k16.row.col.f32.bf16.bf16.f32 "
        "{%0,%1,%2,%3}, {%4,%5,%6,%7}, {%8,%9}, {%0,%1,%2,%3};"
        : "+f"(c[0]), "+f"(c[1]), "+f"(c[2]), "+f"(c[3])
        : "r"(a[0]), "r"(a[1]), "r"(a[2]), "r"(a[3]), "r"(b[0]), "r"(b[1]));
}
__device__ __forceinline__ void ldsm_x4(uint32_t* r, uint32_t addr) {
    asm volatile("ldmatrix.sync.aligned.m8n8.x4.shared.b16 {%0,%1,%2,%3}, [%4];"
                 : "=r"(r[0]), "=r"(r[1]), "=r"(r[2]), "=r"(r[3]) : "r"(addr));
}
// tf32 f32-tile swizzle (enc A)
__device__ __forceinline__ int swoff(int r, int k) {
    return r * 32 + ((((k >> 2) ^ r) & 7) << 2) + (k & 3);
}

// ---------------------------------------------------------------------------
// Kernel 0: prep — dec_w -> bf16 islands; enc_w -> tf32 bits
// ---------------------------------------------------------------------------
__global__ void prep_kernel(const float* __restrict__ dw, const float* __restrict__ ew)
{
    int idx = blockIdx.x * 256 + threadIdx.x;
    if (idx < Cc * KPAD) {
        int m = idx / KPAD, kp = idx % KPAD;
        int g = kp / 56, rem = kp % 56;
        int ky = rem / 8, kx = rem % 8;
        float v = 0.f;
        if (kx < 7) v = dw[m * K2G + (ky * 7 + kx) * 4 + g];
        g_dwb[idx] = (uint16_t)(bf2(v, 0.f) & 0xFFFF);
    } else if (idx < Cc * KPAD + CE * Cc) {
        int j = idx - Cc * KPAD;
        g_wt[j] = tf32rna(ew[j]);
    }
}

// ---------------------------------------------------------------------------
// Kernel 1: enc 1x1 conv on mma.sync tf32 (R13 config, BN=256)
// ---------------------------------------------------------------------------
#define E_SMEM (2 * (8192 + 32768))
#define E_AST(s) ((s) * 8192)
#define E_BST(s) (16384 + (s) * 32768)

__global__ void __launch_bounds__(256, 2) enc_kernel(
    const float* __restrict__ x,
    const float* __restrict__ eg, const float* __restrict__ eb,
    const float* __restrict__ em, const float* __restrict__ ev)
{
    extern __shared__ char esm[];
    const int t = threadIdx.x;
    const int wid = t >> 5, lane = t & 31;
    const int warpN = wid;
    const int n0 = blockIdx.x * 256;
    const int b  = blockIdx.y;

    const float* xb = x + (size_t)b * Cc * THW;

    float cacc[4][4][4];
    #pragma unroll
    for (int i = 0; i < 4; i++)
        #pragma unroll
        for (int j = 0; j < 4; j++)
            #pragma unroll
            for (int r = 0; r < 4; r++) cacc[i][j][r] = 0.f;

    int bpos[4];
    #pragma unroll
    for (int nt = 0; nt < 4; nt++) {
        int n = warpN * 32 + nt * 8 + (lane >> 2);
        bpos[nt] = (((n >> 2) ^ (2 * (lane & 3))) << 2) + (n & 3);
    }

    auto load_chunk = [&](int kc, int s) {
        {
            int e = t, r = e >> 3, c = e & 7;
            cp_async16(smem_u32(esm + E_AST(s) + r * 128 + (((c ^ r) & 7) << 4)),
                       g_wt + r * Cc + kc * 32 + c * 4, 16);
            e = t + 256; r = e >> 3; c = e & 7;
            cp_async16(smem_u32(esm + E_AST(s) + r * 128 + (((c ^ r) & 7) << 4)),
                       g_wt + r * Cc + kc * 32 + c * 4, 16);
        }
        #pragma unroll
        for (int i = 0; i < 8; i++) {
            int e = t + 256 * i;
            int k = e >> 6, j = e & 63;
            uint32_t dst = smem_u32(esm + E_BST(s) + k * 1024
                                    + ((j ^ (2 * (k & 3))) << 4));
            cp_async16(dst, xb + (size_t)(kc * 32 + k) * THW + n0 + j * 4, 16);
        }
    };

    load_chunk(0, 0);
    cp_commit();

    for (int c = 0; c < 8; c++) {
        const int s = c & 1;
        if (c > 0) __syncthreads();
        if (c + 1 < 8) { load_chunk(c + 1, s ^ 1); cp_commit(); cp_wait1(); }
        else cp_wait0();
        __syncthreads();

        const uint32_t* Ab = reinterpret_cast<const uint32_t*>(esm + E_AST(s));
        const uint32_t* Bb = reinterpret_cast<const uint32_t*>(esm + E_BST(s));

        #pragma unroll
        for (int ks = 0; ks < 4; ks++) {
            const int kf = ks * 8 + (lane & 3);
            uint32_t bfr[4][2];
            #pragma unroll
            for (int nt = 0; nt < 4; nt++) {
                bfr[nt][0] = tf32rna(__uint_as_float(Bb[kf * 256 + bpos[nt]]));
                bfr[nt][1] = tf32rna(__uint_as_float(Bb[(kf + 4) * 256 + bpos[nt]]));
            }
            #pragma unroll
            for (int mt = 0; mt < 4; mt++) {
                int r = mt * 16 + (lane >> 2);
                uint32_t afr[4];
                afr[0] = Ab[swoff(r,     kf)];
                afr[1] = Ab[swoff(r + 8, kf)];
                afr[2] = Ab[swoff(r,     kf + 4)];
                afr[3] = Ab[swoff(r + 8, kf + 4)];
                #pragma unroll
                for (int nt = 0; nt < 4; nt++)
                    mma_tf32(cacc[mt][nt], afr, bfr[nt]);
            }
        }
    }

    #pragma unroll
    for (int mt = 0; mt < 4; mt++) {
        int ce0 = mt * 16 + (lane >> 2);
        float inv0  = eg[ce0] * rsqrtf(ev[ce0] + EPSI);
        float bias0 = eb[ce0] - em[ce0] * inv0;
        float inv1  = eg[ce0 + 8] * rsqrtf(ev[ce0 + 8] + EPSI);
        float bias1 = eb[ce0 + 8] - em[ce0 + 8] * inv1;
        uint32_t* op0 = reinterpret_cast<uint32_t*>(
            g_xencb + ((size_t)b * CE + ce0)     * THW + n0);
        uint32_t* op1 = reinterpret_cast<uint32_t*>(
            g_xencb + ((size_t)b * CE + ce0 + 8) * THW + n0);
        #pragma unroll
        for (int nt = 0; nt < 4; nt++) {
            int n = warpN * 32 + nt * 8 + (lane & 3) * 2;
            float a0 = fmaxf(cacc[mt][nt][0] * inv0 + bias0, 0.f);
            float a1 = fmaxf(cacc[mt][nt][1] * inv0 + bias0, 0.f);
            float a2 = fmaxf(cacc[mt][nt][2] * inv1 + bias1, 0.f);
            float a3 = fmaxf(cacc[mt][nt][3] * inv1 + bias1, 0.f);
            op0[n >> 1] = bf2(a0, a1);
            op1[n >> 1] = bf2(a2, a3);
        }
    }
}

// ---------------------------------------------------------------------------
// Kernel 2: corr v6 (R13 config, unchanged)
// ---------------------------------------------------------------------------
#define C_SMEM 54272
#define CX1W(ce, r)    ((ce) * 288 + (r) * 36)
#define CX2W(ce, row)  (4608 + (ce) * 504 + (row) * 36)
#define CWF(ce, ky, k) (12672 + (ce) * 56 + (ky) * 8 + (k))

__global__ void __launch_bounds__(224, 4) corr_kernel(const float* __restrict__ fw)
{
    extern __shared__ float cs[];
    uint32_t* cw = reinterpret_cast<uint32_t*>(cs);
    const int tid = threadIdx.x;
    const int r   = tid & 7;
    const int q   = tid >> 3;
    const int px0 = q * 2;

    const int h0 = blockIdx.x * 8;
    const int tt = blockIdx.y;
    const int b  = blockIdx.z >> 2;
    const int g  = blockIdx.z & 3;
    const int ce0 = g * 16;

    const int t1 = (tt == 0) ? 0 : tt - 1;
    const uint16_t* x1b = g_xencb + (size_t)b * CE * THW + (size_t)t1 * HW;
    const uint16_t* x2b = g_xencb + (size_t)b * CE * THW + (size_t)tt * HW;
    const size_t pixbase = (size_t)b * THW + (size_t)tt * HW + (size_t)h0 * Ww;

    for (int i = tid; i < 16 * 49; i += 224) {
        int ce = i / 49, tap = i % 49;
        cs[CWF(ce, tap / 7, tap % 7)] = fw[((size_t)(ce0 + ce) * Tt + tt) * 49 + tap];
    }
    for (int i = tid; i < 16 * 224; i += 224) {
        int ce = i / 224, rem = i % 224;
        int rr = rem / 28, wi = rem % 28;
        cw[CX1W(ce, rr) + wi] = *reinterpret_cast<const uint32_t*>(
            x1b + (size_t)(ce0 + ce) * THW + (h0 + rr) * Ww + wi * 2);
    }
    for (int i = tid; i < 16 * 448; i += 224) {
        int ce = i / 448, rem = i % 448;
        int row = rem / 32, wi = rem % 32;
        int hy = h0 + row - 3;
        int c0 = wi * 2 - 4;
        uint32_t v = 0;
        if (hy >= 0 && hy < Hh && wi >= 2 && wi <= 29)
            v = *reinterpret_cast<const uint32_t*>(
                x2b + (size_t)(ce0 + ce) * THW + hy * Ww + c0);
        cw[CX2W(ce, row) + wi] = v;
    }
    __syncthreads();

    uint16_t* gb0 = g_xcorrb + (pixbase + r * 56 + px0) * KPAD + (size_t)g * 56;

    #pragma unroll 1
    for (int ky = 0; ky < 7; ky++) {
        float acc[7][2];
        #pragma unroll
        for (int kx = 0; kx < 7; kx++) { acc[kx][0] = 0.f; acc[kx][1] = 0.f; }

        const int zr = r + ky;

        #pragma unroll 4
        for (int ce = 0; ce < 16; ce++) {
            uint32_t yv = cw[CX1W(ce, r) + q];
            float y0 = bflo(yv), y1 = bfhi(yv);
            const uint32_t* zp = &cw[CX2W(ce, zr) + q];
            uint32_t zw0 = zp[0], zw1 = zp[1], zw2 = zp[2], zw3 = zp[3], zw4 = zp[4];
            float z[8];
            z[0] = bfhi(zw0);
            z[1] = bflo(zw1); z[2] = bfhi(zw1);
            z[3] = bflo(zw2); z[4] = bfhi(zw2);
            z[5] = bflo(zw3); z[6] = bfhi(zw3);
            z[7] = bflo(zw4);
            const float* wp = &cs[CWF(ce, ky, 0)];
            float4 w4 = *reinterpret_cast<const float4*>(wp);
            float2 w2 = *reinterpret_cast<const float2*>(wp + 4);
            float  w6 = wp[6];
            float w[7] = {w4.x, w4.y, w4.z, w4.w, w2.x, w2.y, w6};
            #pragma unroll
            for (int kx = 0; kx < 7; kx++) {
                acc[kx][0] += w[kx] * (y0 * z[kx]);
                acc[kx][1] += w[kx] * (y1 * z[kx + 1]);
            }
        }

        const float sc = 1.f / 16.f;
        uint4 v;
        v.x = bf2(acc[0][0] * sc, acc[1][0] * sc);
        v.y = bf2(acc[2][0] * sc, acc[3][0] * sc);
        v.z = bf2(acc[4][0] * sc, acc[5][0] * sc);
        v.w = bf2(acc[6][0] * sc, 0.f);
        *reinterpret_cast<uint4*>(gb0 + ky * 8) = v;
        v.x = bf2(acc[0][1] * sc, acc[1][1] * sc);
        v.y = bf2(acc[2][1] * sc, acc[3][1] * sc);
        v.z = bf2(acc[4][1] * sc, acc[5][1] * sc);
        v.w = bf2(acc[6][1] * sc, 0.f);
        *reinterpret_cast<uint4*>(gb0 + KPAD + ky * 8) = v;
    }
}

// ---------------------------------------------------------------------------
// Kernel 3: dec GEMM bf16 mma + ldmatrix, K-chunk 64 (4 rounds, tail ks=2),
// BM=128, BN=128, 256 thr = 8 warps (2m x 4n), 2-stage cp.async, 2 CTAs/SM,
// m-pair grid interleave. Rows 128B, chunk-XOR swizzle c^(row&7).
// ---------------------------------------------------------------------------
#define D_SMEM (2 * 32768)
#define D_AST(s) ((s) * 32768)
#define D_BST(s) ((s) * 32768 + 16384)

__global__ void __launch_bounds__(256, 2) dec_kernel(
    const float* __restrict__ x,
    const float* __restrict__ dg, const float* __restrict__ db,
    const float* __restrict__ dm, const float* __restrict__ dv,
    float* __restrict__ out)
{
    extern __shared__ char dsm[];
    const int t    = threadIdx.x;
    const int wid  = t >> 5, lane = t & 31;
    const int warpM = wid >> 2;
    const int warpN = wid & 3;

    const int nx = blockIdx.x >> 1;
    const int m0 = (blockIdx.x & 1) * 128;
    const int b  = blockIdx.y;
    const size_t nbase = (size_t)nx * 128;

    const uint16_t* arow = g_dwb + (size_t)m0 * KPAD;
    const uint16_t* brow = g_xcorrb + ((size_t)b * THW + nbase) * KPAD;

    float cacc[4][4][4];
    #pragma unroll
    for (int i = 0; i < 4; i++)
        #pragma unroll
        for (int j = 0; j < 4; j++)
            #pragma unroll
            for (int r = 0; r < 4; r++) cacc[i][j][r] = 0.f;

    // ldmatrix lane geometry: rows of 32 words (64 bf16)
    const int rowBl = warpN * 32 + lane;
    const int r7B   = rowBl & 7;
    const int rAoff = (lane & 7) + ((lane >> 3) & 1) * 8;
    const int khc   = (lane >> 4) & 1;          // A k-half chunk offset

    auto load_chunk = [&](int kc, int s) {      // kc in k-elements (0,64,128,192)
        #pragma unroll
        for (int i = 0; i < 4; i++) {
            int e = t + 256 * i;                // 0..1023
            int row = e >> 3, c = e & 7;
            uint32_t soff = row * 128 + (((c ^ row) & 7) << 4);
            int sz = (kc + c * 8 < KPAD) ? 16 : 0;
            cp_async16(smem_u32(dsm + D_AST(s) + soff),
                       arow + (size_t)row * KPAD + kc + c * 8, sz);
            cp_async16(smem_u32(dsm + D_BST(s) + soff),
                       brow + (size_t)row * KPAD + kc + c * 8, sz);
        }
    };

    load_chunk(0, 0);
    cp_commit();

    for (int c = 0; c < 4; c++) {
        const int s = c & 1;
        if (c > 0) __syncthreads();
        if (c + 1 < 4) { load_chunk((c + 1) * 64, s ^ 1); cp_commit(); cp_wait1(); }
        else cp_wait0();
        __syncthreads();

        const uint32_t* Ab = reinterpret_cast<const uint32_t*>(dsm + D_AST(s));
        const uint32_t* Bb = reinterpret_cast<const uint32_t*>(dsm + D_BST(s));

        auto do_ks = [&](int ks) {
            const int cb = ks * 2;              // 16B-chunk index of lower k-half
            uint32_t bh0[4], bh1[4];
            ldsm_x4(bh0, smem_u32(Bb + rowBl * 32 + (((cb)     ^ r7B) << 2)));
            ldsm_x4(bh1, smem_u32(Bb + rowBl * 32 + (((cb + 1) ^ r7B) << 2)));
            #pragma unroll
            for (int mt = 0; mt < 4; mt++) {
                int rowA = warpM * 64 + mt * 16 + rAoff;
                uint32_t afr[4];
                ldsm_x4(afr, smem_u32(Ab + rowA * 32
                                      + (((cb + khc) ^ (rowA & 7)) << 2)));
                #pragma unroll
                for (int nt = 0; nt < 4; nt++) {
                    uint32_t bfr[2] = {bh0[nt], bh1[nt]};
                    mma_bf16(cacc[mt][nt], afr, bfr);
                }
            }
        };

        do_ks(0);
        do_ks(1);
        if (c < 3) { do_ks(2); do_ks(3); }     // tail round covers only k 192..223
    }

    // Epilogue: BN + residual + ReLU
    #pragma unroll
    for (int mt = 0; mt < 4; mt++) {
        int mrow = m0 + warpM * 64 + mt * 16 + (lane >> 2);
        float inv0  = dg[mrow] * rsqrtf(dv[mrow] + EPSI);
        float bias0 = db[mrow] - dm[mrow] * inv0;
        float inv1  = dg[mrow + 8] * rsqrtf(dv[mrow + 8] + EPSI);
        float bias1 = db[mrow + 8] - dm[mrow + 8] * inv1;
        const float* xr0 = x   + ((size_t)b * Cc + mrow)     * THW + nbase;
        const float* xr1 = x   + ((size_t)b * Cc + mrow + 8) * THW + nbase;
        float*       op0 = out + ((size_t)b * Cc + mrow)     * THW + nbase;
        float*       op1 = out + ((size_t)b * Cc + mrow + 8) * THW + nbase;
        #pragma unroll
        for (int nt = 0; nt < 4; nt++) {
            int n = warpN * 32 + nt * 8 + (lane & 3) * 2;
            float2 r0 = *reinterpret_cast<const float2*>(xr0 + n);
            float2 r1 = *reinterpret_cast<const float2*>(xr1 + n);
            float2 o0, o1;
            o0.x = fmaxf(cacc[mt][nt][0] * inv0 + bias0 + r0.x, 0.f);
            o0.y = fmaxf(cacc[mt][nt][1] * inv0 + bias0 + r0.y, 0.f);
            o1.x = fmaxf(cacc[mt][nt][2] * inv1 + bias1 + r1.x, 0.f);
            o1.y = fmaxf(cacc[mt][nt][3] * inv1 + bias1 + r1.y, 0.f);
            *reinterpret_cast<float2*>(op0 + n) = o0;
            *reinterpret_cast<float2*>(op1 + n) = o1;
        }
    }
}

// ---------------------------------------------------------------------------
extern "C" void kernel_launch(void* const* d_in, const int* in_sizes, int n_in,
                              void* d_out, int out_size)
{
    const float* x     = (const float*)d_in[0];
    const float* enc_w = (const float*)d_in[1];
    const float* eg    = (const float*)d_in[2];
    const float* eb    = (const float*)d_in[3];
    const float* em    = (const float*)d_in[4];
    const float* ev    = (const float*)d_in[5];
    const float* fw    = (const float*)d_in[6];
    const float* dw    = (const float*)d_in[7];
    const float* dg    = (const float*)d_in[8];
    const float* db    = (const float*)d_in[9];
    const float* dm    = (const float*)d_in[10];
    const float* dv    = (const float*)d_in[11];
    float* out = (float*)d_out;

    cudaFuncSetAttribute(enc_kernel,
                         cudaFuncAttributeMaxDynamicSharedMemorySize, E_SMEM);
    cudaFuncSetAttribute(corr_kernel,
                         cudaFuncAttributeMaxDynamicSharedMemorySize, C_SMEM);
    cudaFuncSetAttribute(dec_kernel,
                         cudaFuncAttributeMaxDynamicSharedMemorySize, D_SMEM);

    int prep_n = Cc * KPAD + CE * Cc;
    prep_kernel<<<(prep_n + 255) / 256, 256>>>(dw, enc_w);

    dim3 g1(THW / 256, Bsz);
    enc_kernel<<<g1, 256, E_SMEM>>>(x, eg, eb, em, ev);

    dim3 g2(Hh / 8, Tt, Bsz * Gg);
    corr_kernel<<<g2, 224, C_SMEM>>>(fw);

    dim3 g3(THW / 128 * 2, Bsz);
    dec_kernel<<<g3, 256, D_SMEM>>>(x, dg, db, dm, dv, out);
}

// round 16
// speedup vs baseline: 1.0510x; 1.0126x over previous
#include <cuda_runtime.h>
#include <cuda_bf16.h>
#include <cstdint>

#define Bsz   4
#define Cc    256
#define CE    64
#define Tt    16
#define Hh    56
#define Ww    56
#define HW    3136
#define THW   50176
#define Gg    4
#define K2G   196
#define KPAD  224            // 28 islands of 8 (g*56 + ky*8 + kx, kx<7 valid)
#define EPSI  1e-5f

typedef unsigned long long ull;

// Scratch (device globals: allocation-free rule)
__device__ uint16_t g_xencb[(size_t)Bsz * CE * THW];      // x_enc bf16
__device__ uint16_t g_xcorrb[(size_t)Bsz * THW * KPAD];   // [pixel][k''] bf16
__device__ uint16_t g_dwb[Cc * KPAD];                     // dec_w permuted bf16
__device__ uint32_t g_wt[CE * Cc];                        // enc_w tf32 bits

__device__ __forceinline__ void cp_async16(uint32_t smem_addr, const void* gptr, int src_bytes) {
    asm volatile("cp.async.cg.shared.global [%0], [%1], 16, %2;"
                 :: "r"(smem_addr), "l"(gptr), "r"(src_bytes));
}
__device__ __forceinline__ void cp_commit() { asm volatile("cp.async.commit_group;"); }
__device__ __forceinline__ void cp_wait0()  { asm volatile("cp.async.wait_group 0;"); }
__device__ __forceinline__ void cp_wait1()  { asm volatile("cp.async.wait_group 1;"); }

__device__ __forceinline__ uint32_t tf32rna(float f) {
    uint32_t r; asm("cvt.rna.tf32.f32 %0, %1;" : "=r"(r) : "f"(f)); return r;
}
__device__ __forceinline__ uint32_t bf2(float lo, float hi) {
    uint32_t r; asm("cvt.rn.bf16x2.f32 %0, %1, %2;" : "=r"(r) : "f"(hi), "f"(lo));
    return r;
}
__device__ __forceinline__ float bflo(uint32_t w) { return __uint_as_float(w << 16); }
__device__ __forceinline__ float bfhi(uint32_t w) { return __uint_as_float(w & 0xFFFF0000u); }
__device__ __forceinline__ uint32_t smem_u32(const void* p) {
    return (uint32_t)__cvta_generic_to_shared(p);
}
// f32x2 packed helpers
__device__ __forceinline__ ull packxy(float x, float y) {
    ull r; unsigned a = __float_as_uint(x), b = __float_as_uint(y);
    asm("mov.b64 %0, {%1, %2};" : "=l"(r) : "r"(a), "r"(b));
    return r;
}
__device__ __forceinline__ ull packdup(float x) {
    ull r; unsigned u = __float_as_uint(x);
    asm("mov.b64 %0, {%1, %1};" : "=l"(r) : "r"(u));
    return r;
}
__device__ __forceinline__ ull mul2(ull a, ull b) {
    ull r; asm("mul.rn.f32x2 %0, %1, %2;" : "=l"(r) : "l"(a), "l"(b));
    return r;
}
__device__ __forceinline__ void fma2acc(ull& d, ull a, ull b) {
    asm("fma.rn.f32x2 %0, %1, %2, %0;" : "+l"(d) : "l"(a), "l"(b));
}
__device__ __forceinline__ float2 unpack2(ull v) {
    unsigned lo, hi;
    asm("mov.b64 {%0, %1}, %2;" : "=r"(lo), "=r"(hi) : "l"(v));
    return make_float2(__uint_as_float(lo), __uint_as_float(hi));
}
__device__ __forceinline__ void mma_tf32(float* c, const uint32_t* a, const uint32_t* b) {
    asm volatile(
        "mma.sync.aligned.m16n8k8.row.col.f32.tf32.tf32.f32 "
        "{%0,%1,%2,%3}, {%4,%5,%6,%7}, {%8,%9}, {%0,%1,%2,%3};"
        : "+f"(c[0]), "+f"(c[1]), "+f"(c[2]), "+f"(c[3])
        : "r"(a[0]), "r"(a[1]), "r"(a[2]), "r"(a[3]), "r"(b[0]), "r"(b[1]));
}
__device__ __forceinline__ void mma_bf16(float* c, const uint32_t* a, const uint32_t* b) {
    asm volatile(
        "mma.sync.aligned.m16n8k16.row.col.f32.bf16.bf16.f32 "
        "{%0,%1,%2,%3}, {%4,%5,%6,%7}, {%8,%9}, {%0,%1,%2,%3};"
        : "+f"(c[0]), "+f"(c[1]), "+f"(c[2]), "+f"(c[3])
        : "r"(a[0]), "r"(a[1]), "r"(a[2]), "r"(a[3]), "r"(b[0]), "r"(b[1]));
}
__device__ __forceinline__ void ldsm_x4(uint32_t* r, uint32_t addr) {
    asm volatile("ldmatrix.sync.aligned.m8n8.x4.shared.b16 {%0,%1,%2,%3}, [%4];"
                 : "=r"(r[0]), "=r"(r[1]), "=r"(r[2]), "=r"(r[3]) : "r"(addr));
}
// tf32 f32-tile swizzle (enc A)
__device__ __forceinline__ int swoff(int r, int k) {
    return r * 32 + ((((k >> 2) ^ r) & 7) << 2) + (k & 3);
}

// ---------------------------------------------------------------------------
// Kernel 0: prep — dec_w -> bf16 islands; enc_w -> tf32 bits
// ---------------------------------------------------------------------------
__global__ void prep_kernel(const float* __restrict__ dw, const float* __restrict__ ew)
{
    int idx = blockIdx.x * 256 + threadIdx.x;
    if (idx < Cc * KPAD) {
        int m = idx / KPAD, kp = idx % KPAD;
        int g = kp / 56, rem = kp % 56;
        int ky = rem / 8, kx = rem % 8;
        float v = 0.f;
        if (kx < 7) v = dw[m * K2G + (ky * 7 + kx) * 4 + g];
        g_dwb[idx] = (uint16_t)(bf2(v, 0.f) & 0xFFFF);
    } else if (idx < Cc * KPAD + CE * Cc) {
        int j = idx - Cc * KPAD;
        g_wt[j] = tf32rna(ew[j]);
    }
}

// ---------------------------------------------------------------------------
// Kernel 1: enc 1x1 conv on mma.sync tf32 (unchanged)
// ---------------------------------------------------------------------------
#define E_SMEM (2 * (8192 + 32768))
#define E_AST(s) ((s) * 8192)
#define E_BST(s) (16384 + (s) * 32768)

__global__ void __launch_bounds__(256, 2) enc_kernel(
    const float* __restrict__ x,
    const float* __restrict__ eg, const float* __restrict__ eb,
    const float* __restrict__ em, const float* __restrict__ ev)
{
    extern __shared__ char esm[];
    const int t = threadIdx.x;
    const int wid = t >> 5, lane = t & 31;
    const int warpN = wid;
    const int n0 = blockIdx.x * 256;
    const int b  = blockIdx.y;

    const float* xb = x + (size_t)b * Cc * THW;

    float cacc[4][4][4];
    #pragma unroll
    for (int i = 0; i < 4; i++)
        #pragma unroll
        for (int j = 0; j < 4; j++)
            #pragma unroll
            for (int r = 0; r < 4; r++) cacc[i][j][r] = 0.f;

    int bpos[4];
    #pragma unroll
    for (int nt = 0; nt < 4; nt++) {
        int n = warpN * 32 + nt * 8 + (lane >> 2);
        bpos[nt] = (((n >> 2) ^ (2 * (lane & 3))) << 2) + (n & 3);
    }

    auto load_chunk = [&](int kc, int s) {
        {
            int e = t, r = e >> 3, c = e & 7;
            cp_async16(smem_u32(esm + E_AST(s) + r * 128 + (((c ^ r) & 7) << 4)),
                       g_wt + r * Cc + kc * 32 + c * 4, 16);
            e = t + 256; r = e >> 3; c = e & 7;
            cp_async16(smem_u32(esm + E_AST(s) + r * 128 + (((c ^ r) & 7) << 4)),
                       g_wt + r * Cc + kc * 32 + c * 4, 16);
        }
        #pragma unroll
        for (int i = 0; i < 8; i++) {
            int e = t + 256 * i;
            int k = e >> 6, j = e & 63;
            uint32_t dst = smem_u32(esm + E_BST(s) + k * 1024
                                    + ((j ^ (2 * (k & 3))) << 4));
            cp_async16(dst, xb + (size_t)(kc * 32 + k) * THW + n0 + j * 4, 16);
        }
    };

    load_chunk(0, 0);
    cp_commit();

    for (int c = 0; c < 8; c++) {
        const int s = c & 1;
        if (c > 0) __syncthreads();
        if (c + 1 < 8) { load_chunk(c + 1, s ^ 1); cp_commit(); cp_wait1(); }
        else cp_wait0();
        __syncthreads();

        const uint32_t* Ab = reinterpret_cast<const uint32_t*>(esm + E_AST(s));
        const uint32_t* Bb = reinterpret_cast<const uint32_t*>(esm + E_BST(s));

        #pragma unroll
        for (int ks = 0; ks < 4; ks++) {
            const int kf = ks * 8 + (lane & 3);
            uint32_t bfr[4][2];
            #pragma unroll
            for (int nt = 0; nt < 4; nt++) {
                bfr[nt][0] = tf32rna(__uint_as_float(Bb[kf * 256 + bpos[nt]]));
                bfr[nt][1] = tf32rna(__uint_as_float(Bb[(kf + 4) * 256 + bpos[nt]]));
            }
            #pragma unroll
            for (int mt = 0; mt < 4; mt++) {
                int r = mt * 16 + (lane >> 2);
                uint32_t afr[4];
                afr[0] = Ab[swoff(r,     kf)];
                afr[1] = Ab[swoff(r + 8, kf)];
                afr[2] = Ab[swoff(r,     kf + 4)];
                afr[3] = Ab[swoff(r + 8, kf + 4)];
                #pragma unroll
                for (int nt = 0; nt < 4; nt++)
                    mma_tf32(cacc[mt][nt], afr, bfr[nt]);
            }
        }
    }

    #pragma unroll
    for (int mt = 0; mt < 4; mt++) {
        int ce0 = mt * 16 + (lane >> 2);
        float inv0  = eg[ce0] * rsqrtf(ev[ce0] + EPSI);
        float bias0 = eb[ce0] - em[ce0] * inv0;
        float inv1  = eg[ce0 + 8] * rsqrtf(ev[ce0 + 8] + EPSI);
        float bias1 = eb[ce0 + 8] - em[ce0 + 8] * inv1;
        uint32_t* op0 = reinterpret_cast<uint32_t*>(
            g_xencb + ((size_t)b * CE + ce0)     * THW + n0);
        uint32_t* op1 = reinterpret_cast<uint32_t*>(
            g_xencb + ((size_t)b * CE + ce0 + 8) * THW + n0);
        #pragma unroll
        for (int nt = 0; nt < 4; nt++) {
            int n = warpN * 32 + nt * 8 + (lane & 3) * 2;
            float a0 = fmaxf(cacc[mt][nt][0] * inv0 + bias0, 0.f);
            float a1 = fmaxf(cacc[mt][nt][1] * inv0 + bias0, 0.f);
            float a2 = fmaxf(cacc[mt][nt][2] * inv1 + bias1, 0.f);
            float a3 = fmaxf(cacc[mt][nt][3] * inv1 + bias1, 0.f);
            op0[n >> 1] = bf2(a0, a1);
            op1[n >> 1] = bf2(a2, a3);
        }
    }
}

// ---------------------------------------------------------------------------
// Kernel 2: corr v7 — f32x2 packed mainloop (pixels paired per lane),
// otherwise identical to the measured-best corr v6 (4 CTAs/SM, direct stores).
// ---------------------------------------------------------------------------
#define C_SMEM 54272
#define CX1W(ce, r)    ((ce) * 288 + (r) * 36)
#define CX2W(ce, row)  (4608 + (ce) * 504 + (row) * 36)
#define CWF(ce, ky, k) (12672 + (ce) * 56 + (ky) * 8 + (k))

__global__ void __launch_bounds__(224, 4) corr_kernel(const float* __restrict__ fw)
{
    extern __shared__ float cs[];
    uint32_t* cw = reinterpret_cast<uint32_t*>(cs);
    const int tid = threadIdx.x;
    const int r   = tid & 7;
    const int q   = tid >> 3;
    const int px0 = q * 2;

    const int h0 = blockIdx.x * 8;
    const int tt = blockIdx.y;
    const int b  = blockIdx.z >> 2;
    const int g  = blockIdx.z & 3;
    const int ce0 = g * 16;

    const int t1 = (tt == 0) ? 0 : tt - 1;
    const uint16_t* x1b = g_xencb + (size_t)b * CE * THW + (size_t)t1 * HW;
    const uint16_t* x2b = g_xencb + (size_t)b * CE * THW + (size_t)tt * HW;
    const size_t pixbase = (size_t)b * THW + (size_t)tt * HW + (size_t)h0 * Ww;

    for (int i = tid; i < 16 * 49; i += 224) {
        int ce = i / 49, tap = i % 49;
        cs[CWF(ce, tap / 7, tap % 7)] = fw[((size_t)(ce0 + ce) * Tt + tt) * 49 + tap];
    }
    for (int i = tid; i < 16 * 224; i += 224) {
        int ce = i / 224, rem = i % 224;
        int rr = rem / 28, wi = rem % 28;
        cw[CX1W(ce, rr) + wi] = *reinterpret_cast<const uint32_t*>(
            x1b + (size_t)(ce0 + ce) * THW + (h0 + rr) * Ww + wi * 2);
    }
    for (int i = tid; i < 16 * 448; i += 224) {
        int ce = i / 448, rem = i % 448;
        int row = rem / 32, wi = rem % 32;
        int hy = h0 + row - 3;
        int c0 = wi * 2 - 4;
        uint32_t v = 0;
        if (hy >= 0 && hy < Hh && wi >= 2 && wi <= 29)
            v = *reinterpret_cast<const uint32_t*>(
                x2b + (size_t)(ce0 + ce) * THW + hy * Ww + c0);
        cw[CX2W(ce, row) + wi] = v;
    }
    __syncthreads();

    uint16_t* gb0 = g_xcorrb + (pixbase + r * 56 + px0) * KPAD + (size_t)g * 56;

    #pragma unroll 1
    for (int ky = 0; ky < 7; ky++) {
        ull acc2[7];
        #pragma unroll
        for (int kx = 0; kx < 7; kx++) acc2[kx] = 0ull;

        const int zr = r + ky;

        #pragma unroll 4
        for (int ce = 0; ce < 16; ce++) {
            uint32_t yv = cw[CX1W(ce, r) + q];
            ull yp = packxy(bflo(yv), bfhi(yv));       // {y0, y1}
            const uint32_t* zp = &cw[CX2W(ce, zr) + q];
            uint32_t zw0 = zp[0], zw1 = zp[1], zw2 = zp[2], zw3 = zp[3], zw4 = zp[4];
            float z[8];
            z[0] = bfhi(zw0);
            z[1] = bflo(zw1); z[2] = bfhi(zw1);
            z[3] = bflo(zw2); z[4] = bfhi(zw2);
            z[5] = bflo(zw3); z[6] = bfhi(zw3);
            z[7] = bflo(zw4);
            const float* wp = &cs[CWF(ce, ky, 0)];
            float4 w4 = *reinterpret_cast<const float4*>(wp);
            float2 w2 = *reinterpret_cast<const float2*>(wp + 4);
            float  w6 = wp[6];
            float w[7] = {w4.x, w4.y, w4.z, w4.w, w2.x, w2.y, w6};
            #pragma unroll
            for (int kx = 0; kx < 7; kx++) {
                ull t2 = mul2(yp, packxy(z[kx], z[kx + 1]));   // {y0*z[kx], y1*z[kx+1]}
                fma2acc(acc2[kx], packdup(w[kx]), t2);
            }
        }

        // direct island stores: one uint4 per owned pixel
        const float sc = 1.f / 16.f;
        float2 a0 = unpack2(acc2[0]), a1 = unpack2(acc2[1]);
        float2 a2 = unpack2(acc2[2]), a3 = unpack2(acc2[3]);
        float2 a4 = unpack2(acc2[4]), a5 = unpack2(acc2[5]);
        float2 a6 = unpack2(acc2[6]);
        uint4 v;
        v.x = bf2(a0.x * sc, a1.x * sc);
        v.y = bf2(a2.x * sc, a3.x * sc);
        v.z = bf2(a4.x * sc, a5.x * sc);
        v.w = bf2(a6.x * sc, 0.f);
        *reinterpret_cast<uint4*>(gb0 + ky * 8) = v;
        v.x = bf2(a0.y * sc, a1.y * sc);
        v.y = bf2(a2.y * sc, a3.y * sc);
        v.z = bf2(a4.y * sc, a5.y * sc);
        v.w = bf2(a6.y * sc, 0.f);
        *reinterpret_cast<uint4*>(gb0 + KPAD + ky * 8) = v;
    }
}

// ---------------------------------------------------------------------------
// Kernel 3: dec GEMM bf16 mma + ldmatrix, K-chunk 64 (R15 config, unchanged)
// ---------------------------------------------------------------------------
#define D_SMEM (2 * 32768)
#define D_AST(s) ((s) * 32768)
#define D_BST(s) ((s) * 32768 + 16384)

__global__ void __launch_bounds__(256, 2) dec_kernel(
    const float* __restrict__ x,
    const float* __restrict__ dg, const float* __restrict__ db,
    const float* __restrict__ dm, const float* __restrict__ dv,
    float* __restrict__ out)
{
    extern __shared__ char dsm[];
    const int t    = threadIdx.x;
    const int wid  = t >> 5, lane = t & 31;
    const int warpM = wid >> 2;
    const int warpN = wid & 3;

    const int nx = blockIdx.x >> 1;
    const int m0 = (blockIdx.x & 1) * 128;
    const int b  = blockIdx.y;
    const size_t nbase = (size_t)nx * 128;

    const uint16_t* arow = g_dwb + (size_t)m0 * KPAD;
    const uint16_t* brow = g_xcorrb + ((size_t)b * THW + nbase) * KPAD;

    float cacc[4][4][4];
    #pragma unroll
    for (int i = 0; i < 4; i++)
        #pragma unroll
        for (int j = 0; j < 4; j++)
            #pragma unroll
            for (int r = 0; r < 4; r++) cacc[i][j][r] = 0.f;

    const int rowBl = warpN * 32 + lane;
    const int r7B   = rowBl & 7;
    const int rAoff = (lane & 7) + ((lane >> 3) & 1) * 8;
    const int khc   = (lane >> 4) & 1;

    auto load_chunk = [&](int kc, int s) {
        #pragma unroll
        for (int i = 0; i < 4; i++) {
            int e = t + 256 * i;
            int row = e >> 3, c = e & 7;
            uint32_t soff = row * 128 + (((c ^ row) & 7) << 4);
            int sz = (kc + c * 8 < KPAD) ? 16 : 0;
            cp_async16(smem_u32(dsm + D_AST(s) + soff),
                       arow + (size_t)row * KPAD + kc + c * 8, sz);
            cp_async16(smem_u32(dsm + D_BST(s) + soff),
                       brow + (size_t)row * KPAD + kc + c * 8, sz);
        }
    };

    load_chunk(0, 0);
    cp_commit();

    for (int c = 0; c < 4; c++) {
        const int s = c & 1;
        if (c > 0) __syncthreads();
        if (c + 1 < 4) { load_chunk((c + 1) * 64, s ^ 1); cp_commit(); cp_wait1(); }
        else cp_wait0();
        __syncthreads();

        const uint32_t* Ab = reinterpret_cast<const uint32_t*>(dsm + D_AST(s));
        const uint32_t* Bb = reinterpret_cast<const uint32_t*>(dsm + D_BST(s));

        auto do_ks = [&](int ks) {
            const int cb = ks * 2;
            uint32_t bh0[4], bh1[4];
            ldsm_x4(bh0, smem_u32(Bb + rowBl * 32 + (((cb)     ^ r7B) << 2)));
            ldsm_x4(bh1, smem_u32(Bb + rowBl * 32 + (((cb + 1) ^ r7B) << 2)));
            #pragma unroll
            for (int mt = 0; mt < 4; mt++) {
                int rowA = warpM * 64 + mt * 16 + rAoff;
                uint32_t afr[4];
                ldsm_x4(afr, smem_u32(Ab + rowA * 32
                                      + (((cb + khc) ^ (rowA & 7)) << 2)));
                #pragma unroll
                for (int nt = 0; nt < 4; nt++) {
                    uint32_t bfr[2] = {bh0[nt], bh1[nt]};
                    mma_bf16(cacc[mt][nt], afr, bfr);
                }
            }
        };

        do_ks(0);
        do_ks(1);
        if (c < 3) { do_ks(2); do_ks(3); }
    }

    #pragma unroll
    for (int mt = 0; mt < 4; mt++) {
        int mrow = m0 + warpM * 64 + mt * 16 + (lane >> 2);
        float inv0  = dg[mrow] * rsqrtf(dv[mrow] + EPSI);
        float bias0 = db[mrow] - dm[mrow] * inv0;
        float inv1  = dg[mrow + 8] * rsqrtf(dv[mrow + 8] + EPSI);
        float bias1 = db[mrow + 8] - dm[mrow + 8] * inv1;
        const float* xr0 = x   + ((size_t)b * Cc + mrow)     * THW + nbase;
        const float* xr1 = x   + ((size_t)b * Cc + mrow + 8) * THW + nbase;
        float*       op0 = out + ((size_t)b * Cc + mrow)     * THW + nbase;
        float*       op1 = out + ((size_t)b * Cc + mrow + 8) * THW + nbase;
        #pragma unroll
        for (int nt = 0; nt < 4; nt++) {
            int n = warpN * 32 + nt * 8 + (lane & 3) * 2;
            float2 r0 = *reinterpret_cast<const float2*>(xr0 + n);
            float2 r1 = *reinterpret_cast<const float2*>(xr1 + n);
            float2 o0, o1;
            o0.x = fmaxf(cacc[mt][nt][0] * inv0 + bias0 + r0.x, 0.f);
            o0.y = fmaxf(cacc[mt][nt][1] * inv0 + bias0 + r0.y, 0.f);
            o1.x = fmaxf(cacc[mt][nt][2] * inv1 + bias1 + r1.x, 0.f);
            o1.y = fmaxf(cacc[mt][nt][3] * inv1 + bias1 + r1.y, 0.f);
            *reinterpret_cast<float2*>(op0 + n) = o0;
            *reinterpret_cast<float2*>(op1 + n) = o1;
        }
    }
}

// ---------------------------------------------------------------------------
extern "C" void kernel_launch(void* const* d_in, const int* in_sizes, int n_in,
                              void* d_out, int out_size)
{
    const float* x     = (const float*)d_in[0];
    const float* enc_w = (const float*)d_in[1];
    const float* eg    = (const float*)d_in[2];
    const float* eb    = (const float*)d_in[3];
    const float* em    = (const float*)d_in[4];
    const float* ev    = (const float*)d_in[5];
    const float* fw    = (const float*)d_in[6];
    const float* dw    = (const float*)d_in[7];
    const float* dg    = (const float*)d_in[8];
    const float* db    = (const float*)d_in[9];
    const float* dm    = (const float*)d_in[10];
    const float* dv    = (const float*)d_in[11];
    float* out = (float*)d_out;

    cudaFuncSetAttribute(enc_kernel,
                         cudaFuncAttributeMaxDynamicSharedMemorySize, E_SMEM);
    cudaFuncSetAttribute(corr_kernel,
                         cudaFuncAttributeMaxDynamicSharedMemorySize, C_SMEM);
    cudaFuncSetAttribute(dec_kernel,
                         cudaFuncAttributeMaxDynamicSharedMemorySize, D_SMEM);

    int prep_n = Cc * KPAD + CE * Cc;
    prep_kernel<<<(prep_n + 255) / 256, 256>>>(dw, enc_w);

    dim3 g1(THW / 256, Bsz);
    enc_kernel<<<g1, 256, E_SMEM>>>(x, eg, eb, em, ev);

    dim3 g2(Hh / 8, Tt, Bsz * Gg);
    corr_kernel<<<g2, 224, C_SMEM>>>(fw);

    dim3 g3(THW / 128 * 2, Bsz);
    dec_kernel<<<g3, 256, D_SMEM>>>(x, dg, db, dm, dv, out);
}